// round 10
// baseline (speedup 1.0000x reference)
#include <cuda_runtime.h>
#include <cuda_bf16.h>
#include <cstdint>

// Problem dims
#define BDIM 8192
#define INDIM 1024
#define OUTDIM 4096

// GEMM tiling (mma.sync path — tcgen05 unavailable at harness PTX target sm_103)
#define MT 128
#define NTILE 128
#define KC 64                      // K elements per pipeline chunk (64 bf16 = 128 B/row)
#define NUM_CHUNKS (INDIM / KC)    // 16
#define STAGES 4

#define A_BYTES (MT * 128)         // 16384 (128 rows x 128 B)
#define B_BYTES (NTILE * 128)      // 16384
#define STAGE_BYTES (A_BYTES + B_BYTES)       // 32768
#define SMEM_TOTAL (STAGES * STAGE_BYTES)     // 131072

// ---------------- scratch (no allocs allowed) ----------------
__device__ __nv_bfloat16 g_xb[(size_t)BDIM * INDIM];     // x in bf16, [B, IN]
__device__ __nv_bfloat16 g_wtb[(size_t)OUTDIM * INDIM];  // W^T in bf16, [OUT, IN] (K-major)
__device__ float g_xsq[BDIM];
__device__ float g_wsq[OUTDIM];

// ---------------- PTX helpers ----------------
__device__ __forceinline__ uint32_t smem_u32(const void* p) {
    uint32_t a;
    asm("{ .reg .u64 t; cvta.to.shared.u64 t, %1; cvt.u32.u64 %0, t; }" : "=r"(a) : "l"(p));
    return a;
}

#define CP_ASYNC16(smem_addr, gptr) \
    asm volatile("cp.async.cg.shared.global [%0], [%1], 16;" \
        :: "r"((uint32_t)(smem_addr)), "l"(gptr) : "memory")

#define CP_COMMIT() asm volatile("cp.async.commit_group;" ::: "memory")
#define CP_WAIT_2() asm volatile("cp.async.wait_group 2;" ::: "memory")
#define CP_WAIT_0() asm volatile("cp.async.wait_group 0;" ::: "memory")

#define LDMATRIX_X4(r0, r1, r2, r3, addr) \
    asm volatile("ldmatrix.sync.aligned.m8n8.x4.shared.b16 {%0,%1,%2,%3}, [%4];" \
        : "=r"(r0), "=r"(r1), "=r"(r2), "=r"(r3) : "r"((uint32_t)(addr)))

#define MMA_16816(d, a, b) \
    asm volatile("mma.sync.aligned.m16n8k16.row.col.f32.bf16.bf16.f32 " \
        "{%0,%1,%2,%3}, {%4,%5,%6,%7}, {%8,%9}, {%0,%1,%2,%3};" \
        : "+f"((d)[0]), "+f"((d)[1]), "+f"((d)[2]), "+f"((d)[3]) \
        : "r"((a)[0]), "r"((a)[1]), "r"((a)[2]), "r"((a)[3]), \
          "r"((b)[0]), "r"((b)[1]))

// SW128 atom swizzle on a 128B-row tile: XOR 16B-chunk index (bits 4-6) with row%8 (bits 7-9)
__device__ __forceinline__ uint32_t sw128(uint32_t byte_off) {
    return byte_off ^ ((byte_off >> 3) & 0x70u);
}

// ---------------- block reduce ----------------
__device__ __forceinline__ float block_sum256(float v) {
    #pragma unroll
    for (int o = 16; o; o >>= 1) v += __shfl_xor_sync(0xFFFFFFFFu, v, o);
    __shared__ float sh[8];
    if ((threadIdx.x & 31) == 0) sh[threadIdx.x >> 5] = v;
    __syncthreads();
    if (threadIdx.x < 32) {
        v = (threadIdx.x < 8) ? sh[threadIdx.x] : 0.0f;
        #pragma unroll
        for (int o = 4; o; o >>= 1) v += __shfl_xor_sync(0xFFFFFFFFu, v, o);
    }
    return v;  // valid in thread 0
}

// ---------------- prep kernels ----------------
// x fp32 [B, IN] -> g_xb bf16, g_xsq[b] = sum x^2 (fp32)
__global__ void prep_x_kernel(const float* __restrict__ x) {
    int row = blockIdx.x;
    const float4* xr = (const float4*)(x + (size_t)row * INDIM);
    float4 v = xr[threadIdx.x];
    __nv_bfloat162* xbr = (__nv_bfloat162*)(g_xb + (size_t)row * INDIM);
    xbr[threadIdx.x * 2 + 0] = __floats2bfloat162_rn(v.x, v.y);
    xbr[threadIdx.x * 2 + 1] = __floats2bfloat162_rn(v.z, v.w);
    float s = v.x * v.x + v.y * v.y + v.z * v.z + v.w * v.w;
    s = block_sum256(s);
    if (threadIdx.x == 0) g_xsq[row] = s;
}

// W fp32 [IN, OUT] -> g_wtb bf16 [OUT, IN]
__global__ void prep_wt_kernel(const float* __restrict__ w) {
    __shared__ float t[32][33];
    int o0 = blockIdx.x * 32, k0 = blockIdx.y * 32;
    int tx = threadIdx.x, ty = threadIdx.y;  // (32, 8)
    #pragma unroll
    for (int j = 0; j < 32; j += 8)
        t[ty + j][tx] = w[(size_t)(k0 + ty + j) * OUTDIM + o0 + tx];
    __syncthreads();
    #pragma unroll
    for (int j = 0; j < 32; j += 8)
        g_wtb[(size_t)(o0 + ty + j) * INDIM + k0 + tx] = __float2bfloat16_rn(t[tx][ty + j]);
}

// g_wsq[o] = sum_k wtb[o,k]^2 (fp32 accumulation over bf16 values)
__global__ void prep_wsq_kernel() {
    int row = blockIdx.x;
    const __nv_bfloat162* wr = (const __nv_bfloat162*)(g_wtb + (size_t)row * INDIM);
    __nv_bfloat162 a = wr[threadIdx.x * 2 + 0];
    __nv_bfloat162 b = wr[threadIdx.x * 2 + 1];
    float2 fa = __bfloat1622float2(a), fb = __bfloat1622float2(b);
    float s = fa.x * fa.x + fa.y * fa.y + fb.x * fb.x + fb.y * fb.y;
    s = block_sum256(s);
    if (threadIdx.x == 0) g_wsq[row] = s;
}

// ---------------- GEMM mainloop helpers ----------------
__device__ __forceinline__ void load_stage(uint32_t sA, uint32_t sB,
                                           int m0, int n0, int kc, int tid) {
    // A: 128 rows x 8 x 16B chunks = 1024 chunks; 256 threads x 4
    #pragma unroll
    for (int i = 0; i < 4; i++) {
        int id = tid + 256 * i;
        int row = id >> 3, c = id & 7;
        uint32_t off = sw128((uint32_t)(row * 128 + c * 16));
        const __nv_bfloat16* g = g_xb + (size_t)(m0 + row) * INDIM + kc + c * 8;
        CP_ASYNC16(sA + off, g);
    }
    // B: same shape from W^T
    #pragma unroll
    for (int i = 0; i < 4; i++) {
        int id = tid + 256 * i;
        int row = id >> 3, c = id & 7;
        uint32_t off = sw128((uint32_t)(row * 128 + c * 16));
        const __nv_bfloat16* g = g_wtb + (size_t)(n0 + row) * INDIM + kc + c * 8;
        CP_ASYNC16(sB + off, g);
    }
}

// out[m, n] = g_xsq[m] - 2 * (x @ W)[m, n] + g_wsq[n]
__global__ void __launch_bounds__(256, 1)
rbf_gemm_kernel(float* __restrict__ out) {
    extern __shared__ char smem[];
    uint32_t sb = smem_u32(smem);
    int tid = threadIdx.x;
    int lane = tid & 31;
    int wid = tid >> 5;
    int warp_m = wid & 3;   // 4 warps along M: 32 rows each
    int warp_n = wid >> 2;  // 2 warps along N: 64 cols each

    int n0 = blockIdx.x * NTILE;
    int m0 = blockIdx.y * MT;

    float acc[2][8][4];
    #pragma unroll
    for (int mi = 0; mi < 2; mi++)
        #pragma unroll
        for (int ni = 0; ni < 8; ni++)
            #pragma unroll
            for (int j = 0; j < 4; j++) acc[mi][ni][j] = 0.0f;

    // prologue: fill STAGES-1 stages
    #pragma unroll
    for (int s = 0; s < STAGES - 1; s++) {
        load_stage(sb + s * STAGE_BYTES, sb + s * STAGE_BYTES + A_BYTES,
                   m0, n0, s * KC, tid);
        CP_COMMIT();
    }

    // precomputed per-lane fragment address components
    // A ldmatrix.x4: lanes 0-7 M0(mlo,klo), 8-15 M1(mhi,klo), 16-23 M2(mlo,khi), 24-31 M3(mhi,khi)
    int a_mrow = warp_m * 32 + (((lane >> 3) & 1) << 3) + (lane & 7);
    int a_kbyte = (lane >> 4) << 4;                 // 0 or 16
    // B ldmatrix.x4: lanes 0-7 (nlo,klo), 8-15 (nlo,khi), 16-23 (nhi,klo), 24-31 (nhi,khi)
    int b_nrow0 = warp_n * 64 + ((lane >> 4) << 3) + (lane & 7);
    int b_kbyte = ((lane >> 3) & 1) << 4;           // 0 or 16

    for (int c = 0; c < NUM_CHUNKS; c++) {
        CP_WAIT_2();
        __syncthreads();

        if (c + STAGES - 1 < NUM_CHUNKS) {
            int s = (c + STAGES - 1) & (STAGES - 1);
            load_stage(sb + s * STAGE_BYTES, sb + s * STAGE_BYTES + A_BYTES,
                       m0, n0, (c + STAGES - 1) * KC, tid);
        }
        CP_COMMIT();

        uint32_t aBase = sb + (c & (STAGES - 1)) * STAGE_BYTES;
        uint32_t bBase = aBase + A_BYTES;

        #pragma unroll
        for (int ks = 0; ks < 4; ks++) {
            uint32_t af[2][4];
            uint32_t bf[8][2];
            // A fragments: two m16 blocks
            #pragma unroll
            for (int mi = 0; mi < 2; mi++) {
                uint32_t off = sw128((uint32_t)((a_mrow + mi * 16) * 128 + ks * 32 + a_kbyte));
                LDMATRIX_X4(af[mi][0], af[mi][1], af[mi][2], af[mi][3], aBase + off);
            }
            // B fragments: four n16 groups -> eight n8 fragments
            #pragma unroll
            for (int p = 0; p < 4; p++) {
                uint32_t off = sw128((uint32_t)((b_nrow0 + p * 16) * 128 + ks * 32 + b_kbyte));
                uint32_t r0, r1, r2, r3;
                LDMATRIX_X4(r0, r1, r2, r3, bBase + off);
                bf[p * 2 + 0][0] = r0; bf[p * 2 + 0][1] = r1;
                bf[p * 2 + 1][0] = r2; bf[p * 2 + 1][1] = r3;
            }
            #pragma unroll
            for (int mi = 0; mi < 2; mi++)
                #pragma unroll
                for (int ni = 0; ni < 8; ni++)
                    MMA_16816(acc[mi][ni], af[mi], bf[ni]);
        }
    }
    CP_WAIT_0();

    // ---------------- fused epilogue ----------------
    // acc[mi][ni]: rows m0 + warp_m*32 + mi*16 + lane/4 (+8 for regs 2,3)
    //              cols n0 + warp_n*64 + ni*8 + (lane%4)*2 (+1)
    int mrow = m0 + warp_m * 32 + (lane >> 2);
    int ncol = n0 + warp_n * 64 + (lane & 3) * 2;
    #pragma unroll
    for (int mi = 0; mi < 2; mi++) {
        int r0 = mrow + mi * 16;
        float xs0 = g_xsq[r0];
        float xs1 = g_xsq[r0 + 8];
        float* out0 = out + (size_t)r0 * OUTDIM;
        float* out1 = out + (size_t)(r0 + 8) * OUTDIM;
        #pragma unroll
        for (int ni = 0; ni < 8; ni++) {
            int col = ncol + ni * 8;
            float2 ws = *(const float2*)(g_wsq + col);
            float2 v0, v1;
            v0.x = xs0 + ws.x - 2.0f * acc[mi][ni][0];
            v0.y = xs0 + ws.y - 2.0f * acc[mi][ni][1];
            v1.x = xs1 + ws.x - 2.0f * acc[mi][ni][2];
            v1.y = xs1 + ws.y - 2.0f * acc[mi][ni][3];
            *(float2*)(out0 + col) = v0;
            *(float2*)(out1 + col) = v1;
        }
    }
}

// ---------------- host ----------------
extern "C" void kernel_launch(void* const* d_in, const int* in_sizes, int n_in,
                              void* d_out, int out_size) {
    (void)in_sizes; (void)n_in; (void)out_size;
    const float* x = (const float*)d_in[0];
    const float* w = (const float*)d_in[1];
    float* out = (float*)d_out;

    prep_x_kernel<<<BDIM, 256>>>(x);
    prep_wt_kernel<<<dim3(OUTDIM / 32, INDIM / 32), dim3(32, 8)>>>(w);
    prep_wsq_kernel<<<OUTDIM, 256>>>();

    cudaFuncSetAttribute(rbf_gemm_kernel, cudaFuncAttributeMaxDynamicSharedMemorySize, SMEM_TOTAL);
    rbf_gemm_kernel<<<dim3(OUTDIM / NTILE, BDIM / MT), 256, SMEM_TOTAL>>>(out);
}

// round 11
// speedup vs baseline: 1.1794x; 1.1794x over previous
#include <cuda_runtime.h>
#include <cuda_bf16.h>
#include <cstdint>

// Problem dims
#define BDIM 8192
#define INDIM 1024
#define OUTDIM 4096

// GEMM tiling (mma.sync path — tcgen05 unavailable at harness PTX target sm_103)
#define MT 128
#define NTILE 256
#define NTHREADS 512               // 16 warps: 4 along M x 4 along N
#define KC 64                      // K elements per pipeline chunk (64 bf16 = 128 B/row)
#define NUM_CHUNKS (INDIM / KC)    // 16
#define STAGES 4

#define A_BYTES (MT * 128)         // 16384 (128 rows x 128 B)
#define B_BYTES (NTILE * 128)      // 32768 (256 rows x 128 B)
#define STAGE_BYTES (A_BYTES + B_BYTES)       // 49152
#define SMEM_TOTAL (STAGES * STAGE_BYTES)     // 196608

// ---------------- scratch (no allocs allowed) ----------------
__device__ __nv_bfloat16 g_xb[(size_t)BDIM * INDIM];     // x in bf16, [B, IN]
__device__ __nv_bfloat16 g_wtb[(size_t)OUTDIM * INDIM];  // W^T in bf16, [OUT, IN] (K-major)
__device__ float g_xsq[BDIM];
__device__ float g_wsq[OUTDIM];

// ---------------- PTX helpers ----------------
__device__ __forceinline__ uint32_t smem_u32(const void* p) {
    uint32_t a;
    asm("{ .reg .u64 t; cvta.to.shared.u64 t, %1; cvt.u32.u64 %0, t; }" : "=r"(a) : "l"(p));
    return a;
}

#define CP_ASYNC16(smem_addr, gptr) \
    asm volatile("cp.async.cg.shared.global [%0], [%1], 16;" \
        :: "r"((uint32_t)(smem_addr)), "l"(gptr) : "memory")

#define CP_COMMIT() asm volatile("cp.async.commit_group;" ::: "memory")
#define CP_WAIT_2() asm volatile("cp.async.wait_group 2;" ::: "memory")
#define CP_WAIT_0() asm volatile("cp.async.wait_group 0;" ::: "memory")

#define LDMATRIX_X4(r0, r1, r2, r3, addr) \
    asm volatile("ldmatrix.sync.aligned.m8n8.x4.shared.b16 {%0,%1,%2,%3}, [%4];" \
        : "=r"(r0), "=r"(r1), "=r"(r2), "=r"(r3) : "r"((uint32_t)(addr)))

#define MMA_16816(d, a, b) \
    asm volatile("mma.sync.aligned.m16n8k16.row.col.f32.bf16.bf16.f32 " \
        "{%0,%1,%2,%3}, {%4,%5,%6,%7}, {%8,%9}, {%0,%1,%2,%3};" \
        : "+f"((d)[0]), "+f"((d)[1]), "+f"((d)[2]), "+f"((d)[3]) \
        : "r"((a)[0]), "r"((a)[1]), "r"((a)[2]), "r"((a)[3]), \
          "r"((b)[0]), "r"((b)[1]))

// SW128 atom swizzle on a 128B-row tile: XOR 16B-chunk index (bits 4-6) with row%8 (bits 7-9)
__device__ __forceinline__ uint32_t sw128(uint32_t byte_off) {
    return byte_off ^ ((byte_off >> 3) & 0x70u);
}

// ---------------- block reduce ----------------
__device__ __forceinline__ float block_sum256(float v) {
    #pragma unroll
    for (int o = 16; o; o >>= 1) v += __shfl_xor_sync(0xFFFFFFFFu, v, o);
    __shared__ float sh[8];
    if ((threadIdx.x & 31) == 0) sh[threadIdx.x >> 5] = v;
    __syncthreads();
    if (threadIdx.x < 32) {
        v = (threadIdx.x < 8) ? sh[threadIdx.x] : 0.0f;
        #pragma unroll
        for (int o = 4; o; o >>= 1) v += __shfl_xor_sync(0xFFFFFFFFu, v, o);
    }
    return v;  // valid in thread 0
}

// ---------------- prep kernels ----------------
// x fp32 [B, IN] -> g_xb bf16, g_xsq[b] = sum x^2 (fp32)
__global__ void prep_x_kernel(const float* __restrict__ x) {
    int row = blockIdx.x;
    const float4* xr = (const float4*)(x + (size_t)row * INDIM);
    float4 v = xr[threadIdx.x];
    __nv_bfloat162* xbr = (__nv_bfloat162*)(g_xb + (size_t)row * INDIM);
    xbr[threadIdx.x * 2 + 0] = __floats2bfloat162_rn(v.x, v.y);
    xbr[threadIdx.x * 2 + 1] = __floats2bfloat162_rn(v.z, v.w);
    float s = v.x * v.x + v.y * v.y + v.z * v.z + v.w * v.w;
    s = block_sum256(s);
    if (threadIdx.x == 0) g_xsq[row] = s;
}

// W fp32 [IN, OUT] -> g_wtb bf16 [OUT, IN]
__global__ void prep_wt_kernel(const float* __restrict__ w) {
    __shared__ float t[32][33];
    int o0 = blockIdx.x * 32, k0 = blockIdx.y * 32;
    int tx = threadIdx.x, ty = threadIdx.y;  // (32, 8)
    #pragma unroll
    for (int j = 0; j < 32; j += 8)
        t[ty + j][tx] = w[(size_t)(k0 + ty + j) * OUTDIM + o0 + tx];
    __syncthreads();
    #pragma unroll
    for (int j = 0; j < 32; j += 8)
        g_wtb[(size_t)(o0 + ty + j) * INDIM + k0 + tx] = __float2bfloat16_rn(t[tx][ty + j]);
}

// g_wsq[o] = sum_k wtb[o,k]^2 (fp32 accumulation over bf16 values)
__global__ void prep_wsq_kernel() {
    int row = blockIdx.x;
    const __nv_bfloat162* wr = (const __nv_bfloat162*)(g_wtb + (size_t)row * INDIM);
    __nv_bfloat162 a = wr[threadIdx.x * 2 + 0];
    __nv_bfloat162 b = wr[threadIdx.x * 2 + 1];
    float2 fa = __bfloat1622float2(a), fb = __bfloat1622float2(b);
    float s = fa.x * fa.x + fa.y * fa.y + fb.x * fb.x + fb.y * fb.y;
    s = block_sum256(s);
    if (threadIdx.x == 0) g_wsq[row] = s;
}

// ---------------- GEMM mainloop helpers ----------------
__device__ __forceinline__ void load_stage(uint32_t sA, uint32_t sB,
                                           int m0, int n0, int kc, int tid) {
    // A: 128 rows x 8 x 16B chunks = 1024 chunks; 512 threads x 2
    #pragma unroll
    for (int i = 0; i < 2; i++) {
        int id = tid + NTHREADS * i;
        int row = id >> 3, c = id & 7;
        uint32_t off = sw128((uint32_t)(row * 128 + c * 16));
        const __nv_bfloat16* g = g_xb + (size_t)(m0 + row) * INDIM + kc + c * 8;
        CP_ASYNC16(sA + off, g);
    }
    // B: 256 rows x 8 chunks = 2048 chunks; 512 threads x 4
    #pragma unroll
    for (int i = 0; i < 4; i++) {
        int id = tid + NTHREADS * i;
        int row = id >> 3, c = id & 7;
        uint32_t off = sw128((uint32_t)(row * 128 + c * 16));
        const __nv_bfloat16* g = g_wtb + (size_t)(n0 + row) * INDIM + kc + c * 8;
        CP_ASYNC16(sB + off, g);
    }
}

// out[m, n] = g_xsq[m] - 2 * (x @ W)[m, n] + g_wsq[n]
__global__ void __launch_bounds__(NTHREADS, 1)
rbf_gemm_kernel(float* __restrict__ out) {
    extern __shared__ char smem[];
    uint32_t sb = smem_u32(smem);
    int tid = threadIdx.x;
    int lane = tid & 31;
    int wid = tid >> 5;
    int warp_m = wid & 3;   // 4 warps along M: 32 rows each
    int warp_n = wid >> 2;  // 4 warps along N: 64 cols each

    int n0 = blockIdx.x * NTILE;
    int m0 = blockIdx.y * MT;

    float acc[2][8][4];
    #pragma unroll
    for (int mi = 0; mi < 2; mi++)
        #pragma unroll
        for (int ni = 0; ni < 8; ni++)
            #pragma unroll
            for (int j = 0; j < 4; j++) acc[mi][ni][j] = 0.0f;

    // prologue: fill STAGES-1 stages
    #pragma unroll
    for (int s = 0; s < STAGES - 1; s++) {
        load_stage(sb + s * STAGE_BYTES, sb + s * STAGE_BYTES + A_BYTES,
                   m0, n0, s * KC, tid);
        CP_COMMIT();
    }

    // precomputed per-lane fragment address components
    // A ldmatrix.x4: lanes 0-7 M0(mlo,klo), 8-15 M1(mhi,klo), 16-23 M2(mlo,khi), 24-31 M3(mhi,khi)
    int a_mrow = warp_m * 32 + (((lane >> 3) & 1) << 3) + (lane & 7);
    int a_kbyte = (lane >> 4) << 4;                 // 0 or 16
    // B ldmatrix.x4: lanes 0-7 (nlo,klo), 8-15 (nlo,khi), 16-23 (nhi,klo), 24-31 (nhi,khi)
    int b_nrow0 = warp_n * 64 + ((lane >> 4) << 3) + (lane & 7);
    int b_kbyte = ((lane >> 3) & 1) << 4;           // 0 or 16

    for (int c = 0; c < NUM_CHUNKS; c++) {
        CP_WAIT_2();
        __syncthreads();

        if (c + STAGES - 1 < NUM_CHUNKS) {
            int s = (c + STAGES - 1) & (STAGES - 1);
            load_stage(sb + s * STAGE_BYTES, sb + s * STAGE_BYTES + A_BYTES,
                       m0, n0, (c + STAGES - 1) * KC, tid);
        }
        CP_COMMIT();

        uint32_t aBase = sb + (c & (STAGES - 1)) * STAGE_BYTES;
        uint32_t bBase = aBase + A_BYTES;

        #pragma unroll
        for (int ks = 0; ks < 4; ks++) {
            uint32_t af[2][4];
            uint32_t bf[8][2];
            // A fragments: two m16 blocks
            #pragma unroll
            for (int mi = 0; mi < 2; mi++) {
                uint32_t off = sw128((uint32_t)((a_mrow + mi * 16) * 128 + ks * 32 + a_kbyte));
                LDMATRIX_X4(af[mi][0], af[mi][1], af[mi][2], af[mi][3], aBase + off);
            }
            // B fragments: four n16 groups -> eight n8 fragments
            #pragma unroll
            for (int p = 0; p < 4; p++) {
                uint32_t off = sw128((uint32_t)((b_nrow0 + p * 16) * 128 + ks * 32 + b_kbyte));
                uint32_t r0, r1, r2, r3;
                LDMATRIX_X4(r0, r1, r2, r3, bBase + off);
                bf[p * 2 + 0][0] = r0; bf[p * 2 + 0][1] = r1;
                bf[p * 2 + 1][0] = r2; bf[p * 2 + 1][1] = r3;
            }
            #pragma unroll
            for (int mi = 0; mi < 2; mi++)
                #pragma unroll
                for (int ni = 0; ni < 8; ni++)
                    MMA_16816(acc[mi][ni], af[mi], bf[ni]);
        }
    }
    CP_WAIT_0();

    // ---------------- fused epilogue ----------------
    // acc[mi][ni]: rows m0 + warp_m*32 + mi*16 + lane/4 (+8 for regs 2,3)
    //              cols n0 + warp_n*64 + ni*8 + (lane%4)*2 (+1)
    int mrow = m0 + warp_m * 32 + (lane >> 2);
    int ncol = n0 + warp_n * 64 + (lane & 3) * 2;
    #pragma unroll
    for (int mi = 0; mi < 2; mi++) {
        int r0 = mrow + mi * 16;
        float xs0 = g_xsq[r0];
        float xs1 = g_xsq[r0 + 8];
        float* out0 = out + (size_t)r0 * OUTDIM;
        float* out1 = out + (size_t)(r0 + 8) * OUTDIM;
        #pragma unroll
        for (int ni = 0; ni < 8; ni++) {
            int col = ncol + ni * 8;
            float2 ws = *(const float2*)(g_wsq + col);
            float2 v0, v1;
            v0.x = xs0 + ws.x - 2.0f * acc[mi][ni][0];
            v0.y = xs0 + ws.y - 2.0f * acc[mi][ni][1];
            v1.x = xs1 + ws.x - 2.0f * acc[mi][ni][2];
            v1.y = xs1 + ws.y - 2.0f * acc[mi][ni][3];
            *(float2*)(out0 + col) = v0;
            *(float2*)(out1 + col) = v1;
        }
    }
}

// ---------------- host ----------------
extern "C" void kernel_launch(void* const* d_in, const int* in_sizes, int n_in,
                              void* d_out, int out_size) {
    (void)in_sizes; (void)n_in; (void)out_size;
    const float* x = (const float*)d_in[0];
    const float* w = (const float*)d_in[1];
    float* out = (float*)d_out;

    prep_x_kernel<<<BDIM, 256>>>(x);
    prep_wt_kernel<<<dim3(OUTDIM / 32, INDIM / 32), dim3(32, 8)>>>(w);
    prep_wsq_kernel<<<OUTDIM, 256>>>();

    cudaFuncSetAttribute(rbf_gemm_kernel, cudaFuncAttributeMaxDynamicSharedMemorySize, SMEM_TOTAL);
    rbf_gemm_kernel<<<dim3(OUTDIM / NTILE, BDIM / MT), NTHREADS, SMEM_TOTAL>>>(out);
}

// round 12
// speedup vs baseline: 1.2804x; 1.0856x over previous
#include <cuda_runtime.h>
#include <cuda_bf16.h>
#include <cstdint>

// Problem dims
#define BDIM 8192
#define INDIM 1024
#define OUTDIM 4096

// GEMM tiling (mma.sync path — tcgen05 unavailable at harness PTX target sm_103)
// 128x128 CTA tile, 256 threads (8 warps = 4M x 2N, warp tile 32x64),
// 3-stage cp.async pipeline, 96KB SMEM/CTA -> 2 CTAs/SM for barrier overlap.
#define MT 128
#define NTILE 128
#define NTHREADS 256
#define KC 64                      // K elements per pipeline chunk (64 bf16 = 128 B/row)
#define NUM_CHUNKS (INDIM / KC)    // 16
#define STAGES 3

#define A_BYTES (MT * 128)         // 16384
#define B_BYTES (NTILE * 128)      // 16384
#define STAGE_BYTES (A_BYTES + B_BYTES)       // 32768
#define SMEM_TOTAL (STAGES * STAGE_BYTES)     // 98304 -> 2 CTAs/SM

// ---------------- scratch (no allocs allowed) ----------------
__device__ __nv_bfloat16 g_xb[(size_t)BDIM * INDIM];     // x in bf16, [B, IN]
__device__ __nv_bfloat16 g_wtb[(size_t)OUTDIM * INDIM];  // W^T in bf16, [OUT, IN] (K-major)
__device__ float g_xsq[BDIM];
__device__ float g_wsq[OUTDIM];

// ---------------- PTX helpers ----------------
__device__ __forceinline__ uint32_t smem_u32(const void* p) {
    uint32_t a;
    asm("{ .reg .u64 t; cvta.to.shared.u64 t, %1; cvt.u32.u64 %0, t; }" : "=r"(a) : "l"(p));
    return a;
}

#define CP_ASYNC16(smem_addr, gptr) \
    asm volatile("cp.async.cg.shared.global [%0], [%1], 16;" \
        :: "r"((uint32_t)(smem_addr)), "l"(gptr) : "memory")

#define CP_COMMIT() asm volatile("cp.async.commit_group;" ::: "memory")
#define CP_WAIT_1() asm volatile("cp.async.wait_group 1;" ::: "memory")
#define CP_WAIT_0() asm volatile("cp.async.wait_group 0;" ::: "memory")

#define LDMATRIX_X4(r0, r1, r2, r3, addr) \
    asm volatile("ldmatrix.sync.aligned.m8n8.x4.shared.b16 {%0,%1,%2,%3}, [%4];" \
        : "=r"(r0), "=r"(r1), "=r"(r2), "=r"(r3) : "r"((uint32_t)(addr)))

#define MMA_16816(d, a, b) \
    asm volatile("mma.sync.aligned.m16n8k16.row.col.f32.bf16.bf16.f32 " \
        "{%0,%1,%2,%3}, {%4,%5,%6,%7}, {%8,%9}, {%0,%1,%2,%3};" \
        : "+f"((d)[0]), "+f"((d)[1]), "+f"((d)[2]), "+f"((d)[3]) \
        : "r"((a)[0]), "r"((a)[1]), "r"((a)[2]), "r"((a)[3]), \
          "r"((b)[0]), "r"((b)[1]))

// SW128 atom swizzle on a 128B-row tile: XOR 16B-chunk index (bits 4-6) with row%8 (bits 7-9)
__device__ __forceinline__ uint32_t sw128(uint32_t byte_off) {
    return byte_off ^ ((byte_off >> 3) & 0x70u);
}

// ---------------- block reduce ----------------
__device__ __forceinline__ float block_sum256(float v) {
    #pragma unroll
    for (int o = 16; o; o >>= 1) v += __shfl_xor_sync(0xFFFFFFFFu, v, o);
    __shared__ float sh[8];
    if ((threadIdx.x & 31) == 0) sh[threadIdx.x >> 5] = v;
    __syncthreads();
    if (threadIdx.x < 32) {
        v = (threadIdx.x < 8) ? sh[threadIdx.x] : 0.0f;
        #pragma unroll
        for (int o = 4; o; o >>= 1) v += __shfl_xor_sync(0xFFFFFFFFu, v, o);
    }
    return v;  // valid in thread 0
}

// ---------------- prep kernels ----------------
// x fp32 [B, IN] -> g_xb bf16, g_xsq[b] = sum x^2 (fp32)
__global__ void prep_x_kernel(const float* __restrict__ x) {
    int row = blockIdx.x;
    const float4* xr = (const float4*)(x + (size_t)row * INDIM);
    float4 v = xr[threadIdx.x];
    __nv_bfloat162* xbr = (__nv_bfloat162*)(g_xb + (size_t)row * INDIM);
    xbr[threadIdx.x * 2 + 0] = __floats2bfloat162_rn(v.x, v.y);
    xbr[threadIdx.x * 2 + 1] = __floats2bfloat162_rn(v.z, v.w);
    float s = v.x * v.x + v.y * v.y + v.z * v.z + v.w * v.w;
    s = block_sum256(s);
    if (threadIdx.x == 0) g_xsq[row] = s;
}

// W fp32 [IN, OUT] -> g_wtb bf16 [OUT, IN]
__global__ void prep_wt_kernel(const float* __restrict__ w) {
    __shared__ float t[32][33];
    int o0 = blockIdx.x * 32, k0 = blockIdx.y * 32;
    int tx = threadIdx.x, ty = threadIdx.y;  // (32, 8)
    #pragma unroll
    for (int j = 0; j < 32; j += 8)
        t[ty + j][tx] = w[(size_t)(k0 + ty + j) * OUTDIM + o0 + tx];
    __syncthreads();
    #pragma unroll
    for (int j = 0; j < 32; j += 8)
        g_wtb[(size_t)(o0 + ty + j) * INDIM + k0 + tx] = __float2bfloat16_rn(t[tx][ty + j]);
}

// g_wsq[o] = sum_k wtb[o,k]^2 (fp32 accumulation over bf16 values)
__global__ void prep_wsq_kernel() {
    int row = blockIdx.x;
    const __nv_bfloat162* wr = (const __nv_bfloat162*)(g_wtb + (size_t)row * INDIM);
    __nv_bfloat162 a = wr[threadIdx.x * 2 + 0];
    __nv_bfloat162 b = wr[threadIdx.x * 2 + 1];
    float2 fa = __bfloat1622float2(a), fb = __bfloat1622float2(b);
    float s = fa.x * fa.x + fa.y * fa.y + fb.x * fb.x + fb.y * fb.y;
    s = block_sum256(s);
    if (threadIdx.x == 0) g_wsq[row] = s;
}

// ---------------- GEMM mainloop helpers ----------------
__device__ __forceinline__ void load_stage(uint32_t sA, uint32_t sB,
                                           int m0, int n0, int kc, int tid) {
    // A: 128 rows x 8 x 16B chunks = 1024 chunks; 256 threads x 4
    #pragma unroll
    for (int i = 0; i < 4; i++) {
        int id = tid + NTHREADS * i;
        int row = id >> 3, c = id & 7;
        uint32_t off = sw128((uint32_t)(row * 128 + c * 16));
        const __nv_bfloat16* g = g_xb + (size_t)(m0 + row) * INDIM + kc + c * 8;
        CP_ASYNC16(sA + off, g);
    }
    // B: same shape from W^T
    #pragma unroll
    for (int i = 0; i < 4; i++) {
        int id = tid + NTHREADS * i;
        int row = id >> 3, c = id & 7;
        uint32_t off = sw128((uint32_t)(row * 128 + c * 16));
        const __nv_bfloat16* g = g_wtb + (size_t)(n0 + row) * INDIM + kc + c * 8;
        CP_ASYNC16(sB + off, g);
    }
}

// stage index for chunk c (mod 3 without division in the hot loop: small LUT)
__device__ __forceinline__ int stage_of(int c) {
    // NUM_CHUNKS=16, STAGES=3: c % 3
    return c - (c / 3) * 3;
}

// out[m, n] = g_xsq[m] - 2 * (x @ W)[m, n] + g_wsq[n]
__global__ void __launch_bounds__(NTHREADS, 2)
rbf_gemm_kernel(float* __restrict__ out) {
    extern __shared__ char smem[];
    uint32_t sb = smem_u32(smem);
    int tid = threadIdx.x;
    int lane = tid & 31;
    int wid = tid >> 5;
    int warp_m = wid & 3;   // 4 warps along M: 32 rows each
    int warp_n = wid >> 2;  // 2 warps along N: 64 cols each

    int n0 = blockIdx.x * NTILE;
    int m0 = blockIdx.y * MT;

    float acc[2][8][4];
    #pragma unroll
    for (int mi = 0; mi < 2; mi++)
        #pragma unroll
        for (int ni = 0; ni < 8; ni++)
            #pragma unroll
            for (int j = 0; j < 4; j++) acc[mi][ni][j] = 0.0f;

    // prologue: fill STAGES-1 = 2 stages
    #pragma unroll
    for (int s = 0; s < STAGES - 1; s++) {
        load_stage(sb + s * STAGE_BYTES, sb + s * STAGE_BYTES + A_BYTES,
                   m0, n0, s * KC, tid);
        CP_COMMIT();
    }

    // precomputed per-lane fragment address components
    // A ldmatrix.x4: lanes 0-7 M0(mlo,klo), 8-15 M1(mhi,klo), 16-23 M2(mlo,khi), 24-31 M3(mhi,khi)
    int a_mrow = warp_m * 32 + (((lane >> 3) & 1) << 3) + (lane & 7);
    int a_kbyte = (lane >> 4) << 4;                 // 0 or 16
    // B ldmatrix.x4: lanes 0-7 (nlo,klo), 8-15 (nlo,khi), 16-23 (nhi,klo), 24-31 (nhi,khi)
    int b_nrow0 = warp_n * 64 + ((lane >> 4) << 3) + (lane & 7);
    int b_kbyte = ((lane >> 3) & 1) << 4;           // 0 or 16

    int rd_stage = 0;   // stage holding chunk c
    int wr_stage = 2;   // stage to write chunk c+2 into
    for (int c = 0; c < NUM_CHUNKS; c++) {
        CP_WAIT_1();
        __syncthreads();

        if (c + STAGES - 1 < NUM_CHUNKS) {
            load_stage(sb + wr_stage * STAGE_BYTES,
                       sb + wr_stage * STAGE_BYTES + A_BYTES,
                       m0, n0, (c + STAGES - 1) * KC, tid);
        }
        CP_COMMIT();

        uint32_t aBase = sb + rd_stage * STAGE_BYTES;
        uint32_t bBase = aBase + A_BYTES;

        #pragma unroll
        for (int ks = 0; ks < 4; ks++) {
            uint32_t af[2][4];
            uint32_t bf[8][2];
            // A fragments: two m16 blocks
            #pragma unroll
            for (int mi = 0; mi < 2; mi++) {
                uint32_t off = sw128((uint32_t)((a_mrow + mi * 16) * 128 + ks * 32 + a_kbyte));
                LDMATRIX_X4(af[mi][0], af[mi][1], af[mi][2], af[mi][3], aBase + off);
            }
            // B fragments: four n16 groups -> eight n8 fragments
            #pragma unroll
            for (int p = 0; p < 4; p++) {
                uint32_t off = sw128((uint32_t)((b_nrow0 + p * 16) * 128 + ks * 32 + b_kbyte));
                uint32_t r0, r1, r2, r3;
                LDMATRIX_X4(r0, r1, r2, r3, bBase + off);
                bf[p * 2 + 0][0] = r0; bf[p * 2 + 0][1] = r1;
                bf[p * 2 + 1][0] = r2; bf[p * 2 + 1][1] = r3;
            }
            #pragma unroll
            for (int mi = 0; mi < 2; mi++)
                #pragma unroll
                for (int ni = 0; ni < 8; ni++)
                    MMA_16816(acc[mi][ni], af[mi], bf[ni]);
        }

        rd_stage = (rd_stage == STAGES - 1) ? 0 : rd_stage + 1;
        wr_stage = (wr_stage == STAGES - 1) ? 0 : wr_stage + 1;
    }
    CP_WAIT_0();

    // ---------------- fused epilogue ----------------
    // acc[mi][ni]: rows m0 + warp_m*32 + mi*16 + lane/4 (+8 for regs 2,3)
    //              cols n0 + warp_n*64 + ni*8 + (lane%4)*2 (+1)
    int mrow = m0 + warp_m * 32 + (lane >> 2);
    int ncol = n0 + warp_n * 64 + (lane & 3) * 2;
    #pragma unroll
    for (int mi = 0; mi < 2; mi++) {
        int r0 = mrow + mi * 16;
        float xs0 = g_xsq[r0];
        float xs1 = g_xsq[r0 + 8];
        float* out0 = out + (size_t)r0 * OUTDIM;
        float* out1 = out + (size_t)(r0 + 8) * OUTDIM;
        #pragma unroll
        for (int ni = 0; ni < 8; ni++) {
            int col = ncol + ni * 8;
            float2 ws = *(const float2*)(g_wsq + col);
            float2 v0, v1;
            v0.x = xs0 + ws.x - 2.0f * acc[mi][ni][0];
            v0.y = xs0 + ws.y - 2.0f * acc[mi][ni][1];
            v1.x = xs1 + ws.x - 2.0f * acc[mi][ni][2];
            v1.y = xs1 + ws.y - 2.0f * acc[mi][ni][3];
            *(float2*)(out0 + col) = v0;
            *(float2*)(out1 + col) = v1;
        }
    }
}

// ---------------- host ----------------
extern "C" void kernel_launch(void* const* d_in, const int* in_sizes, int n_in,
                              void* d_out, int out_size) {
    (void)in_sizes; (void)n_in; (void)out_size;
    const float* x = (const float*)d_in[0];
    const float* w = (const float*)d_in[1];
    float* out = (float*)d_out;

    prep_x_kernel<<<BDIM, 256>>>(x);
    prep_wt_kernel<<<dim3(OUTDIM / 32, INDIM / 32), dim3(32, 8)>>>(w);
    prep_wsq_kernel<<<OUTDIM, 256>>>();

    cudaFuncSetAttribute(rbf_gemm_kernel, cudaFuncAttributeMaxDynamicSharedMemorySize, SMEM_TOTAL);
    rbf_gemm_kernel<<<dim3(OUTDIM / NTILE, BDIM / MT), NTHREADS, SMEM_TOTAL>>>(out);
}